// round 10
// baseline (speedup 1.0000x reference)
#include <cuda_runtime.h>
#include <cuda_bf16.h>
#include <stdint.h>

// ---------------------------------------------------------------------------
// C[B,256] = x_scalar[B,256] @ W_s[256,256] + b_s
// out = [caps: B x 32 x 16 (cols 0..7 = C slice, 8..15 = 0)] ++ [x_vector copy]
// W_v / b_v dead (e3nn TP output identically zero).
// bf16 hi/lo 3-pass split for fp32-grade accuracy through HMMA.
// ---------------------------------------------------------------------------
#define KDIM      256
#define NDIM      256
#define TILE_M    32
#define NTHREADS  256

// Dynamic smem layout (3 CTAs/SM: 66560 B each, 199680 total)
#define SM_BIAS   0                       // 1024 B
#define SM_A      1024                    // 2 splits x 16 KB (32 rows x 512 B, swizzled)
#define SM_W      (SM_A + 32768)          // 2 bufs x 16 KB (per-kstep hi+lo fragments)
#define SMEM_TOTAL (SM_W + 32768)         // 66560 B

// Pre-packed W fragments (B operand of mma.m16n8k16, hi/lo bf16 splits)
__device__ __align__(16) unsigned char g_Bhi[131072];
__device__ __align__(16) unsigned char g_Blo[131072];

// ---------------------------------------------------------------------------
// helpers
// ---------------------------------------------------------------------------
__device__ __forceinline__ uint32_t smem_u32(const void* p) {
    uint32_t a;
    asm("{ .reg .u64 t; cvta.to.shared.u64 t, %1; cvt.u32.u64 %0, t; }" : "=r"(a) : "l"(p));
    return a;
}
__device__ __forceinline__ uint32_t pack_bf16x2(float x, float y) {
    __nv_bfloat162 t;
    t.x = __float2bfloat16(x);
    t.y = __float2bfloat16(y);
    return *(uint32_t*)&t;
}
__device__ __forceinline__ void ldm_x4(uint32_t* r, uint32_t addr) {
    asm volatile("ldmatrix.sync.aligned.m8n8.x4.shared.b16 {%0,%1,%2,%3}, [%4];"
                 : "=r"(r[0]), "=r"(r[1]), "=r"(r[2]), "=r"(r[3]) : "r"(addr));
}
__device__ __forceinline__ uint4 lds128(uint32_t a) {
    uint4 v;
    asm volatile("ld.shared.v4.b32 {%0,%1,%2,%3}, [%4];"
                 : "=r"(v.x), "=r"(v.y), "=r"(v.z), "=r"(v.w) : "r"(a));
    return v;
}
__device__ __forceinline__ void mma_bf16(float* c, const uint32_t* a, uint32_t b0, uint32_t b1) {
    asm volatile("mma.sync.aligned.m16n8k16.row.col.f32.bf16.bf16.f32 "
                 "{%0,%1,%2,%3}, {%4,%5,%6,%7}, {%8,%9}, {%0,%1,%2,%3};"
                 : "+f"(c[0]), "+f"(c[1]), "+f"(c[2]), "+f"(c[3])
                 : "r"(a[0]), "r"(a[1]), "r"(a[2]), "r"(a[3]), "r"(b0), "r"(b1));
}
#define CP_ASYNC16(s, g) \
    asm volatile("cp.async.cg.shared.global [%0], [%1], 16;" :: "r"(s), "l"(g) : "memory")
#define CP_COMMIT()  asm volatile("cp.async.commit_group;" ::: "memory")
#define CP_WAIT0()   asm volatile("cp.async.wait_group 0;" ::: "memory")

// A-tile smem address: per split, 512 B rows, 16B-granule XOR swizzle
__device__ __forceinline__ uint32_t a_frag_addr(uint32_t sb, int split, int mrow,
                                                int ks, int lane) {
    int i   = lane & 7;
    int sel = lane >> 3;
    int row = mrow + i + ((sel & 1) << 3);
    int gl  = (ks << 1) + (sel >> 1);
    return sb + SM_A + split * 16384 + row * 512 + ((gl ^ (row & 7)) << 4);
}

// ---------------------------------------------------------------------------
// Prologue: pack W_s (fp32 [K][N]) into bf16 hi/lo B-fragment layout.
// 16B unit index = ((ks*4 + g)*4 + p)*32 + lane
// ---------------------------------------------------------------------------
__global__ void prep_W_kernel(const float* __restrict__ Ws) {
    int idx = blockIdx.x * blockDim.x + threadIdx.x;
    if (idx >= KDIM * NDIM) return;
    int k = idx >> 8;
    int n = idx & 255;
    float w = Ws[idx];
    __nv_bfloat16 hi = __float2bfloat16(w);
    __nv_bfloat16 lo = __float2bfloat16(w - __bfloat162float(hi));

    int ks = k >> 4, kr = k & 15;
    int lane = (n & 7) * 4 + ((kr & 7) >> 1);
    int g = n >> 6;
    int p = (n >> 4) & 3;
    int t = (n >> 3) & 1;
    uint32_t off = (uint32_t)((((ks * 4 + g) * 4 + p) * 32 + lane) * 16
                              + t * 8 + ((kr >> 3) << 2) + ((kr & 1) << 1));
    *(__nv_bfloat16*)(g_Bhi + off) = hi;
    *(__nv_bfloat16*)(g_Blo + off) = lo;
}

// ---------------------------------------------------------------------------
// Main kernel: 4096 CTAs x 256 thr (3 CTAs/SM, 24 warps/SM), tile M=32 N=256;
// W streamed per-kstep (double-buffered cp.async), vec copy latency-hidden,
// fused interleave/zero/bias epilogue.
// ---------------------------------------------------------------------------
__global__ __launch_bounds__(NTHREADS, 3)
void caps_kernel(const float* __restrict__ xs,
                 const float* __restrict__ xv,
                 const float* __restrict__ bs,
                 float* __restrict__ out,
                 int Btot) {
    extern __shared__ char smem[];
    const uint32_t sb = smem_u32(smem);
    const int tid  = threadIdx.x;
    const int wid  = tid >> 5;
    const int lane = tid & 31;
    const int g    = wid & 3;            // N group (64 cols)
    const int mblk = (wid >> 2) * 16;    // M block (0 or 16)
    const long row0 = (long)blockIdx.x * TILE_M;

    // bias -> smem
    ((float*)smem)[tid] = bs[tid];

    // prefetch W kstep 0 into buf 0 (overlaps A staging)
    {
        uint32_t e = (uint32_t)tid * 16;       // 0..4095
        CP_ASYNC16(sb + SM_W + e, (const char*)g_Bhi + e);
        CP_ASYNC16(sb + SM_W + 4096 + e, (const char*)g_Bhi + 4096 + e);
        CP_ASYNC16(sb + SM_W + 8192 + e, (const char*)g_Blo + e);
        CP_ASYNC16(sb + SM_W + 12288 + e, (const char*)g_Blo + 4096 + e);
        CP_COMMIT();
    }

    // ---- stage A tile: fp32 -> bf16 hi/lo, swizzled smem (32 rows) ----
    #pragma unroll
    for (int j = 0; j < 8; ++j) {
        int idx = tid + j * NTHREADS;          // 0..2047 float4
        int row = idx >> 6;
        int k   = (idx & 63) << 2;
        float4 v = *(const float4*)(xs + (row0 + row) * KDIM + k);
        uint32_t h01 = pack_bf16x2(v.x, v.y);
        uint32_t h23 = pack_bf16x2(v.z, v.w);
        float hx = __bfloat162float(__float2bfloat16(v.x));
        float hy = __bfloat162float(__float2bfloat16(v.y));
        float hz = __bfloat162float(__float2bfloat16(v.z));
        float hw = __bfloat162float(__float2bfloat16(v.w));
        uint32_t l01 = pack_bf16x2(v.x - hx, v.y - hy);
        uint32_t l23 = pack_bf16x2(v.z - hz, v.w - hw);
        int gl = k >> 3;
        uint32_t off = (uint32_t)(row * 512 + ((gl ^ (row & 7)) << 4) + ((k & 7) << 1));
        *(uint2*)(smem + SM_A + off)         = make_uint2(h01, h23);
        *(uint2*)(smem + SM_A + 16384 + off) = make_uint2(l01, l23);
    }

    float acc[8][4];
    #pragma unroll
    for (int b = 0; b < 8; ++b)
        #pragma unroll
        for (int c = 0; c < 4; ++c) acc[b][c] = 0.f;

    // x_vector passthrough copy (3072 float4 per CTA, 12 slices of 256)
    const float4* vsrc = (const float4*)xv;
    float4* vdst = (float4*)(out + (long)Btot * 512);
    const long vbase = (long)blockIdx.x * 3072;    // 32 rows * 384 floats / 4

    // ---- main pipeline: 16 ksteps ----
    for (int ks = 0; ks < 16; ++ks) {
        CP_WAIT0();
        __syncthreads();
        if (ks < 15) {      // prefetch kstep ks+1 into other buffer
            uint32_t db = sb + SM_W + (uint32_t)(((ks + 1) & 1) * 16384);
            const char* sH = (const char*)g_Bhi + (ks + 1) * 8192;
            const char* sL = (const char*)g_Blo + (ks + 1) * 8192;
            uint32_t e = (uint32_t)tid * 16;
            CP_ASYNC16(db + e, sH + e);
            CP_ASYNC16(db + 4096 + e, sH + 4096 + e);
            CP_ASYNC16(db + 8192 + e, sL + e);
            CP_ASYNC16(db + 12288 + e, sL + 4096 + e);
            CP_COMMIT();
        }
        // vec-copy slice: LDG issued before MMAs (latency hidden), STG after
        float4 v0;
        const bool dovec = (ks < 12);
        long vi = vbase + (long)ks * 256 + tid;
        if (dovec) v0 = vsrc[vi];

        const uint32_t wb = sb + SM_W + (uint32_t)((ks & 1) * 16384 + g * 2048 + lane * 16);
        uint32_t ah[4], al[4];
        ldm_x4(ah, a_frag_addr(sb, 0, mblk, ks, lane));
        ldm_x4(al, a_frag_addr(sb, 1, mblk, ks, lane));
        #pragma unroll
        for (int p = 0; p < 4; ++p) {
            uint4 bh = lds128(wb + p * 512);
            uint4 bl = lds128(wb + 8192 + p * 512);
            mma_bf16(acc[2 * p],     ah, bh.x, bh.y);   // hi*hi
            mma_bf16(acc[2 * p + 1], ah, bh.z, bh.w);
            mma_bf16(acc[2 * p],     ah, bl.x, bl.y);   // hi*lo
            mma_bf16(acc[2 * p + 1], ah, bl.z, bl.w);
            mma_bf16(acc[2 * p],     al, bh.x, bh.y);   // lo*hi
            mma_bf16(acc[2 * p + 1], al, bh.z, bh.w);
        }

        if (dovec) vdst[vi] = v0;
    }

    // ---- epilogue: bias add + capsule interleave (8 data + 8 zero floats) ----
    const float* bias = (const float*)smem;
    const float2 z2 = make_float2(0.f, 0.f);
    #pragma unroll
    for (int nt = 0; nt < 8; ++nt) {
        float2 bc = *(const float2*)(bias + g * 64 + nt * 8 + (lane & 3) * 2);
        const int cap = g * 8 + nt;
        #pragma unroll
        for (int hf = 0; hf < 2; ++hf) {
            long row = row0 + mblk + (lane >> 2) + hf * 8;
            float2 d;
            d.x = acc[nt][hf * 2 + 0] + bc.x;
            d.y = acc[nt][hf * 2 + 1] + bc.y;
            float* pr = out + row * 512 + cap * 16 + (lane & 3) * 2;
            *(float2*)pr = d;
            *(float2*)(pr + 8) = z2;
        }
    }
}

// ---------------------------------------------------------------------------
// Launch
// ---------------------------------------------------------------------------
extern "C" void kernel_launch(void* const* d_in, const int* in_sizes, int n_in,
                              void* d_out, int out_size) {
    const float* xs = (const float*)d_in[0];   // x_scalar [B,256]
    const float* xv = (const float*)d_in[1];   // x_vector [B,128,3]
    const float* Ws = (const float*)d_in[2];   // W_s [256,256]
    const float* bs = (const float*)d_in[3];   // b_s [256]
    float* out = (float*)d_out;

    int Btot = in_sizes[0] / KDIM;

    prep_W_kernel<<<(KDIM * NDIM + 255) / 256, 256>>>(Ws);

    cudaFuncSetAttribute(caps_kernel,
                         cudaFuncAttributeMaxDynamicSharedMemorySize, SMEM_TOTAL);
    caps_kernel<<<Btot / TILE_M, NTHREADS, SMEM_TOTAL>>>(xs, xv, bs, out, Btot);
}

// round 14
// speedup vs baseline: 1.0436x; 1.0436x over previous
#include <cuda_runtime.h>
#include <cuda_bf16.h>
#include <stdint.h>

// ---------------------------------------------------------------------------
// C[B,256] = x_scalar[B,256] @ W_s[256,256] + b_s
// out = [caps: B x 32 x 16 (cols 0..7 = C slice, 8..15 = 0)] ++ [x_vector copy]
// W_v / b_v dead (e3nn TP output identically zero).
// bf16 hi/lo 3-pass split for fp32-grade accuracy through HMMA.
// M=64 tile, 2 CTAs/SM, W streamed through a 3-stage cp.async ring with
// prefetch distance 2 (wait_group 1 => near-zero barrier stall).
// ---------------------------------------------------------------------------
#define KDIM      256
#define NDIM      256
#define TILE_M    64
#define NTHREADS  256

// Dynamic smem layout (2 CTAs/SM: 115712 B each)
#define SM_BIAS   0                       // 1024 B
#define SM_A      1024                    // 2 splits x 32 KB (64 rows x 512 B, swizzled)
#define SM_W      (SM_A + 65536)          // 3 stages x 16 KB (per-kstep hi+lo fragments)
#define SMEM_TOTAL (SM_W + 3 * 16384)    // 115712 B

// Pre-packed W fragments (B operand of mma.m16n8k16, hi/lo bf16 splits)
__device__ __align__(16) unsigned char g_Bhi[131072];
__device__ __align__(16) unsigned char g_Blo[131072];

// ---------------------------------------------------------------------------
// helpers
// ---------------------------------------------------------------------------
__device__ __forceinline__ uint32_t smem_u32(const void* p) {
    uint32_t a;
    asm("{ .reg .u64 t; cvta.to.shared.u64 t, %1; cvt.u32.u64 %0, t; }" : "=r"(a) : "l"(p));
    return a;
}
__device__ __forceinline__ uint32_t pack_bf16x2(float x, float y) {
    __nv_bfloat162 t;
    t.x = __float2bfloat16(x);
    t.y = __float2bfloat16(y);
    return *(uint32_t*)&t;
}
__device__ __forceinline__ void ldm_x4(uint32_t* r, uint32_t addr) {
    asm volatile("ldmatrix.sync.aligned.m8n8.x4.shared.b16 {%0,%1,%2,%3}, [%4];"
                 : "=r"(r[0]), "=r"(r[1]), "=r"(r[2]), "=r"(r[3]) : "r"(addr));
}
__device__ __forceinline__ uint4 lds128(uint32_t a) {
    uint4 v;
    asm volatile("ld.shared.v4.b32 {%0,%1,%2,%3}, [%4];"
                 : "=r"(v.x), "=r"(v.y), "=r"(v.z), "=r"(v.w) : "r"(a));
    return v;
}
__device__ __forceinline__ void mma_bf16(float* c, const uint32_t* a, uint32_t b0, uint32_t b1) {
    asm volatile("mma.sync.aligned.m16n8k16.row.col.f32.bf16.bf16.f32 "
                 "{%0,%1,%2,%3}, {%4,%5,%6,%7}, {%8,%9}, {%0,%1,%2,%3};"
                 : "+f"(c[0]), "+f"(c[1]), "+f"(c[2]), "+f"(c[3])
                 : "r"(a[0]), "r"(a[1]), "r"(a[2]), "r"(a[3]), "r"(b0), "r"(b1));
}
#define CP_ASYNC16(s, g) \
    asm volatile("cp.async.cg.shared.global [%0], [%1], 16;" :: "r"(s), "l"(g) : "memory")
#define CP_COMMIT()  asm volatile("cp.async.commit_group;" ::: "memory")
#define CP_WAIT1()   asm volatile("cp.async.wait_group 1;" ::: "memory")

// A-tile smem address: per split, 512 B rows, 16B-granule XOR swizzle
__device__ __forceinline__ uint32_t a_frag_addr(uint32_t sb, int split, int mrow,
                                                int ks, int lane) {
    int i   = lane & 7;
    int sel = lane >> 3;
    int row = mrow + i + ((sel & 1) << 3);
    int gl  = (ks << 1) + (sel >> 1);
    return sb + SM_A + split * 32768 + row * 512 + ((gl ^ (row & 7)) << 4);
}

// ---------------------------------------------------------------------------
// Prologue: pack W_s (fp32 [K][N]) into bf16 hi/lo B-fragment layout.
// 16B unit index = ((ks*4 + g)*4 + p)*32 + lane
// ---------------------------------------------------------------------------
__global__ void prep_W_kernel(const float* __restrict__ Ws) {
    int idx = blockIdx.x * blockDim.x + threadIdx.x;
    if (idx >= KDIM * NDIM) return;
    int k = idx >> 8;
    int n = idx & 255;
    float w = Ws[idx];
    __nv_bfloat16 hi = __float2bfloat16(w);
    __nv_bfloat16 lo = __float2bfloat16(w - __bfloat162float(hi));

    int ks = k >> 4, kr = k & 15;
    int lane = (n & 7) * 4 + ((kr & 7) >> 1);
    int g = n >> 6;
    int p = (n >> 4) & 3;
    int t = (n >> 3) & 1;
    uint32_t off = (uint32_t)((((ks * 4 + g) * 4 + p) * 32 + lane) * 16
                              + t * 8 + ((kr >> 3) << 2) + ((kr & 1) << 1));
    *(__nv_bfloat16*)(g_Bhi + off) = hi;
    *(__nv_bfloat16*)(g_Blo + off) = lo;
}

// issue one kstep's W fragments (16 KB: 8 KB hi + 8 KB lo) into ring stage
__device__ __forceinline__ void prefetch_W(uint32_t sb, int ks, int tid) {
    uint32_t db = sb + SM_W + (uint32_t)((ks % 3) * 16384);
    const char* sH = (const char*)g_Bhi + ks * 8192;
    const char* sL = (const char*)g_Blo + ks * 8192;
    uint32_t e = (uint32_t)tid * 16;           // 0..4095 (first half)
    CP_ASYNC16(db + e, sH + e);
    CP_ASYNC16(db + 4096 + e, sH + 4096 + e);
    CP_ASYNC16(db + 8192 + e, sL + e);
    CP_ASYNC16(db + 12288 + e, sL + 4096 + e);
    CP_COMMIT();
}

// ---------------------------------------------------------------------------
// Main kernel: 2048 CTAs x 256 thr (2 CTAs/SM), tile M=64 N=256.
// ---------------------------------------------------------------------------
__global__ __launch_bounds__(NTHREADS, 2)
void caps_kernel(const float* __restrict__ xs,
                 const float* __restrict__ xv,
                 const float* __restrict__ bs,
                 float* __restrict__ out,
                 int Btot) {
    extern __shared__ char smem[];
    const uint32_t sb = smem_u32(smem);
    const int tid  = threadIdx.x;
    const int wid  = tid >> 5;
    const int lane = tid & 31;
    const int g    = wid & 3;          // N group (64 cols)
    const int mblk = (wid >> 2) * 32;  // M block
    const long row0 = (long)blockIdx.x * TILE_M;

    // bias -> smem
    ((float*)smem)[tid] = bs[tid];

    // prefetch W ksteps 0 and 1 (two commit groups in flight)
    prefetch_W(sb, 0, tid);
    prefetch_W(sb, 1, tid);

    // ---- stage A tile: fp32 -> bf16 hi/lo, swizzled smem ----
    #pragma unroll
    for (int j = 0; j < 16; ++j) {
        int idx = tid + j * NTHREADS;          // 0..4095 float4
        int row = idx >> 6;
        int k   = (idx & 63) << 2;
        float4 v = *(const float4*)(xs + (row0 + row) * KDIM + k);
        uint32_t h01 = pack_bf16x2(v.x, v.y);
        uint32_t h23 = pack_bf16x2(v.z, v.w);
        float hx = __bfloat162float(__float2bfloat16(v.x));
        float hy = __bfloat162float(__float2bfloat16(v.y));
        float hz = __bfloat162float(__float2bfloat16(v.z));
        float hw = __bfloat162float(__float2bfloat16(v.w));
        uint32_t l01 = pack_bf16x2(v.x - hx, v.y - hy);
        uint32_t l23 = pack_bf16x2(v.z - hz, v.w - hw);
        int gl = k >> 3;
        uint32_t off = (uint32_t)(row * 512 + ((gl ^ (row & 7)) << 4) + ((k & 7) << 1));
        *(uint2*)(smem + SM_A + off)         = make_uint2(h01, h23);
        *(uint2*)(smem + SM_A + 32768 + off) = make_uint2(l01, l23);
    }

    float acc[2][8][4];
    #pragma unroll
    for (int a = 0; a < 2; ++a)
        #pragma unroll
        for (int b = 0; b < 8; ++b)
            #pragma unroll
            for (int c = 0; c < 4; ++c) acc[a][b][c] = 0.f;

    // x_vector passthrough copy (6144 float4 per CTA, 12 slices of 512)
    const float4* vsrc = (const float4*)xv;
    float4* vdst = (float4*)(out + (long)Btot * 512);
    const long vbase = (long)blockIdx.x * 6144;   // 64 rows * 384 floats / 4

    // ---- main pipeline: 16 ksteps, 3-stage ring, prefetch distance 2 ----
    for (int ks = 0; ks < 16; ++ks) {
        CP_WAIT1();              // oldest in-flight group (this kstep) done
        __syncthreads();         // data visible to all; stage (ks+2)%3 free
        if (ks + 2 < 16) prefetch_W(sb, ks + 2, tid);

        // vec-copy slice: LDGs early (latency hidden under MMAs), STGs late
        float4 v0, v1;
        const bool dovec = (ks < 12);
        long vi = vbase + (long)ks * 512 + tid;
        if (dovec) {
            v0 = vsrc[vi];
            v1 = vsrc[vi + 256];
        }

        const uint32_t wb = sb + SM_W + (uint32_t)((ks % 3) * 16384 + g * 2048 + lane * 16);
        uint32_t ah0[4], ah1[4], al0[4], al1[4];
        ldm_x4(ah0, a_frag_addr(sb, 0, mblk,      ks, lane));
        ldm_x4(ah1, a_frag_addr(sb, 0, mblk + 16, ks, lane));
        ldm_x4(al0, a_frag_addr(sb, 1, mblk,      ks, lane));
        ldm_x4(al1, a_frag_addr(sb, 1, mblk + 16, ks, lane));
        #pragma unroll
        for (int p = 0; p < 4; ++p) {
            uint4 bh = lds128(wb + p * 512);
            uint4 bl = lds128(wb + 8192 + p * 512);
            // hi * hi
            mma_bf16(acc[0][2 * p],     ah0, bh.x, bh.y);
            mma_bf16(acc[1][2 * p],     ah1, bh.x, bh.y);
            mma_bf16(acc[0][2 * p + 1], ah0, bh.z, bh.w);
            mma_bf16(acc[1][2 * p + 1], ah1, bh.z, bh.w);
            // hi * lo
            mma_bf16(acc[0][2 * p],     ah0, bl.x, bl.y);
            mma_bf16(acc[1][2 * p],     ah1, bl.x, bl.y);
            mma_bf16(acc[0][2 * p + 1], ah0, bl.z, bl.w);
            mma_bf16(acc[1][2 * p + 1], ah1, bl.z, bl.w);
            // lo * hi
            mma_bf16(acc[0][2 * p],     al0, bh.x, bh.y);
            mma_bf16(acc[1][2 * p],     al1, bh.x, bh.y);
            mma_bf16(acc[0][2 * p + 1], al0, bh.z, bh.w);
            mma_bf16(acc[1][2 * p + 1], al1, bh.z, bh.w);
        }

        if (dovec) {
            vdst[vi] = v0;
            vdst[vi + 256] = v1;
        }
    }

    // ---- epilogue: bias add + capsule interleave (8 data + 8 zero floats) ----
    const float* bias = (const float*)smem;
    const float2 z2 = make_float2(0.f, 0.f);
    #pragma unroll
    for (int nt = 0; nt < 8; ++nt) {
        float2 bc = *(const float2*)(bias + g * 64 + nt * 8 + (lane & 3) * 2);
        const int cap = g * 8 + nt;
        #pragma unroll
        for (int mt = 0; mt < 2; ++mt) {
            #pragma unroll
            for (int hf = 0; hf < 2; ++hf) {
                long row = row0 + mblk + mt * 16 + (lane >> 2) + hf * 8;
                float2 d;
                d.x = acc[mt][nt][hf * 2 + 0] + bc.x;
                d.y = acc[mt][nt][hf * 2 + 1] + bc.y;
                float* pr = out + row * 512 + cap * 16 + (lane & 3) * 2;
                *(float2*)pr = d;
                *(float2*)(pr + 8) = z2;
            }
        }
    }
}

// ---------------------------------------------------------------------------
// Launch
// ---------------------------------------------------------------------------
extern "C" void kernel_launch(void* const* d_in, const int* in_sizes, int n_in,
                              void* d_out, int out_size) {
    const float* xs = (const float*)d_in[0];   // x_scalar [B,256]
    const float* xv = (const float*)d_in[1];   // x_vector [B,128,3]
    const float* Ws = (const float*)d_in[2];   // W_s [256,256]
    const float* bs = (const float*)d_in[3];   // b_s [256]
    float* out = (float*)d_out;

    int Btot = in_sizes[0] / KDIM;

    prep_W_kernel<<<(KDIM * NDIM + 255) / 256, 256>>>(Ws);

    cudaFuncSetAttribute(caps_kernel,
                         cudaFuncAttributeMaxDynamicSharedMemorySize, SMEM_TOTAL);
    caps_kernel<<<Btot / TILE_M, NTHREADS, SMEM_TOTAL>>>(xs, xv, bs, out, Btot);
}

// round 15
// speedup vs baseline: 1.1480x; 1.1001x over previous
#include <cuda_runtime.h>
#include <cuda_bf16.h>
#include <stdint.h>

// ---------------------------------------------------------------------------
// C[B,256] = x_scalar[B,256] @ W_s[256,256] + b_s
// out = [caps: B x 32 x 16 (cols 0..7 = C slice, 8..15 = 0)] ++ [x_vector copy]
// W_v / b_v dead (e3nn TP output identically zero).
// bf16 hi/lo 3-pass split for fp32-grade accuracy through HMMA.
//
// Role-specialized grid: bid%3==2 -> pure x_vector copy CTA (DRAM streamer),
// else -> GEMM CTA (M=64 tile, per-kstep double-buffered W, fused epilogue).
// Interleaved roles co-schedule a DRAM streamer next to a tensor burner on
// every SM, overlapping the two bottlenecks across CTAs instead of phases.
// ---------------------------------------------------------------------------
#define KDIM      256
#define NDIM      256
#define TILE_M    64
#define NTHREADS  256
#define GRID_GEMM 2048
#define GRID_COPY 1024
#define GRID_ALL  (GRID_GEMM + GRID_COPY)

// Dynamic smem layout (2 CTAs/SM: 99328 B each)
#define SM_BIAS   0                       // 1024 B
#define SM_A      1024                    // 2 splits x 32 KB (64 rows x 512 B, swizzled)
#define SM_W      (SM_A + 65536)          // 2 bufs x 16 KB (per-kstep hi+lo fragments)
#define SMEM_TOTAL (SM_W + 32768)         // 99328 B

// Pre-packed W fragments (B operand of mma.m16n8k16, hi/lo bf16 splits)
__device__ __align__(16) unsigned char g_Bhi[131072];
__device__ __align__(16) unsigned char g_Blo[131072];

// ---------------------------------------------------------------------------
// helpers
// ---------------------------------------------------------------------------
__device__ __forceinline__ uint32_t smem_u32(const void* p) {
    uint32_t a;
    asm("{ .reg .u64 t; cvta.to.shared.u64 t, %1; cvt.u32.u64 %0, t; }" : "=r"(a) : "l"(p));
    return a;
}
__device__ __forceinline__ uint32_t pack_bf16x2(float x, float y) {
    __nv_bfloat162 t;
    t.x = __float2bfloat16(x);
    t.y = __float2bfloat16(y);
    return *(uint32_t*)&t;
}
__device__ __forceinline__ void ldm_x4(uint32_t* r, uint32_t addr) {
    asm volatile("ldmatrix.sync.aligned.m8n8.x4.shared.b16 {%0,%1,%2,%3}, [%4];"
                 : "=r"(r[0]), "=r"(r[1]), "=r"(r[2]), "=r"(r[3]) : "r"(addr));
}
__device__ __forceinline__ uint4 lds128(uint32_t a) {
    uint4 v;
    asm volatile("ld.shared.v4.b32 {%0,%1,%2,%3}, [%4];"
                 : "=r"(v.x), "=r"(v.y), "=r"(v.z), "=r"(v.w) : "r"(a));
    return v;
}
__device__ __forceinline__ void mma_bf16(float* c, const uint32_t* a, uint32_t b0, uint32_t b1) {
    asm volatile("mma.sync.aligned.m16n8k16.row.col.f32.bf16.bf16.f32 "
                 "{%0,%1,%2,%3}, {%4,%5,%6,%7}, {%8,%9}, {%0,%1,%2,%3};"
                 : "+f"(c[0]), "+f"(c[1]), "+f"(c[2]), "+f"(c[3])
                 : "r"(a[0]), "r"(a[1]), "r"(a[2]), "r"(a[3]), "r"(b0), "r"(b1));
}
#define CP_ASYNC16(s, g) \
    asm volatile("cp.async.cg.shared.global [%0], [%1], 16;" :: "r"(s), "l"(g) : "memory")
#define CP_COMMIT()  asm volatile("cp.async.commit_group;" ::: "memory")
#define CP_WAIT0()   asm volatile("cp.async.wait_group 0;" ::: "memory")

// A-tile smem address: per split, 512 B rows, 16B-granule XOR swizzle
__device__ __forceinline__ uint32_t a_frag_addr(uint32_t sb, int split, int mrow,
                                                int ks, int lane) {
    int i   = lane & 7;
    int sel = lane >> 3;
    int row = mrow + i + ((sel & 1) << 3);
    int gl  = (ks << 1) + (sel >> 1);
    return sb + SM_A + split * 32768 + row * 512 + ((gl ^ (row & 7)) << 4);
}

// ---------------------------------------------------------------------------
// Prologue: pack W_s (fp32 [K][N]) into bf16 hi/lo B-fragment layout.
// 16B unit index = ((ks*4 + g)*4 + p)*32 + lane
// ---------------------------------------------------------------------------
__global__ void prep_W_kernel(const float* __restrict__ Ws) {
    int idx = blockIdx.x * blockDim.x + threadIdx.x;
    if (idx >= KDIM * NDIM) return;
    int k = idx >> 8;
    int n = idx & 255;
    float w = Ws[idx];
    __nv_bfloat16 hi = __float2bfloat16(w);
    __nv_bfloat16 lo = __float2bfloat16(w - __bfloat162float(hi));

    int ks = k >> 4, kr = k & 15;
    int lane = (n & 7) * 4 + ((kr & 7) >> 1);
    int g = n >> 6;
    int p = (n >> 4) & 3;
    int t = (n >> 3) & 1;
    uint32_t off = (uint32_t)((((ks * 4 + g) * 4 + p) * 32 + lane) * 16
                              + t * 8 + ((kr >> 3) << 2) + ((kr & 1) << 1));
    *(__nv_bfloat16*)(g_Bhi + off) = hi;
    *(__nv_bfloat16*)(g_Blo + off) = lo;
}

// ---------------------------------------------------------------------------
// Main kernel
// ---------------------------------------------------------------------------
__global__ __launch_bounds__(NTHREADS, 2)
void caps_kernel(const float* __restrict__ xs,
                 const float* __restrict__ xv,
                 const float* __restrict__ bs,
                 float* __restrict__ out,
                 int Btot) {
    const int bid = blockIdx.x;
    const int tid = threadIdx.x;

    // ======================= COPY CTA (bid % 3 == 2) =======================
    if ((bid % 3) == 2) {
        const int cid = bid / 3;                    // 0..1023
        const float4* __restrict__ vsrc = (const float4*)xv;
        float4* __restrict__ vdst = (float4*)(out + (long)Btot * 512);
        // Btot*384 floats / 4 = Btot*96 float4 ; per CTA = Btot*96/1024
        const long per = (long)Btot * 96 / GRID_COPY;   // 12288 for B=131072
        long base = (long)cid * per + tid;
        const long end = (long)cid * per + per;
        // 48 float4 per thread; unrolled batches keep many LDGs in flight
        #pragma unroll 4
        for (long i = base; i < end; i += NTHREADS)
            vdst[i] = vsrc[i];
        return;
    }

    // ======================= GEMM CTA ======================================
    extern __shared__ char smem[];
    const uint32_t sb = smem_u32(smem);
    const int wid  = tid >> 5;
    const int lane = tid & 31;
    const int g    = wid & 3;          // N group (64 cols)
    const int mblk = (wid >> 2) * 32;  // M block
    const int gid  = (bid / 3) * 2 + (bid % 3);   // 0..2047 dense GEMM index
    const long row0 = (long)gid * TILE_M;

    // bias -> smem
    ((float*)smem)[tid] = bs[tid];

    // prefetch W kstep 0 into buf 0 (overlaps A staging)
    {
        uint32_t e = (uint32_t)tid * 16;
        CP_ASYNC16(sb + SM_W + e, (const char*)g_Bhi + e);
        CP_ASYNC16(sb + SM_W + 4096 + e, (const char*)g_Bhi + 4096 + e);
        CP_ASYNC16(sb + SM_W + 8192 + e, (const char*)g_Blo + e);
        CP_ASYNC16(sb + SM_W + 12288 + e, (const char*)g_Blo + 4096 + e);
        CP_COMMIT();
    }

    // ---- stage A tile: fp32 -> bf16 hi/lo, swizzled smem ----
    #pragma unroll
    for (int j = 0; j < 16; ++j) {
        int idx = tid + j * NTHREADS;          // 0..4095 float4
        int row = idx >> 6;
        int k   = (idx & 63) << 2;
        float4 v = *(const float4*)(xs + (row0 + row) * KDIM + k);
        uint32_t h01 = pack_bf16x2(v.x, v.y);
        uint32_t h23 = pack_bf16x2(v.z, v.w);
        float hx = __bfloat162float(__float2bfloat16(v.x));
        float hy = __bfloat162float(__float2bfloat16(v.y));
        float hz = __bfloat162float(__float2bfloat16(v.z));
        float hw = __bfloat162float(__float2bfloat16(v.w));
        uint32_t l01 = pack_bf16x2(v.x - hx, v.y - hy);
        uint32_t l23 = pack_bf16x2(v.z - hz, v.w - hw);
        int gl = k >> 3;
        uint32_t off = (uint32_t)(row * 512 + ((gl ^ (row & 7)) << 4) + ((k & 7) << 1));
        *(uint2*)(smem + SM_A + off)         = make_uint2(h01, h23);
        *(uint2*)(smem + SM_A + 32768 + off) = make_uint2(l01, l23);
    }

    float acc[2][8][4];
    #pragma unroll
    for (int a = 0; a < 2; ++a)
        #pragma unroll
        for (int b = 0; b < 8; ++b)
            #pragma unroll
            for (int c = 0; c < 4; ++c) acc[a][b][c] = 0.f;

    // ---- main pipeline: 16 ksteps, per-kstep double-buffered W ----
    for (int ks = 0; ks < 16; ++ks) {
        CP_WAIT0();
        __syncthreads();
        if (ks < 15) {      // prefetch kstep ks+1 into other buffer
            uint32_t db = sb + SM_W + (uint32_t)(((ks + 1) & 1) * 16384);
            const char* sH = (const char*)g_Bhi + (ks + 1) * 8192;
            const char* sL = (const char*)g_Blo + (ks + 1) * 8192;
            uint32_t e = (uint32_t)tid * 16;
            CP_ASYNC16(db + e, sH + e);
            CP_ASYNC16(db + 4096 + e, sH + 4096 + e);
            CP_ASYNC16(db + 8192 + e, sL + e);
            CP_ASYNC16(db + 12288 + e, sL + 4096 + e);
            CP_COMMIT();
        }

        const uint32_t wb = sb + SM_W + (uint32_t)((ks & 1) * 16384 + g * 2048 + lane * 16);
        uint32_t ah0[4], ah1[4], al0[4], al1[4];
        ldm_x4(ah0, a_frag_addr(sb, 0, mblk,      ks, lane));
        ldm_x4(ah1, a_frag_addr(sb, 0, mblk + 16, ks, lane));
        ldm_x4(al0, a_frag_addr(sb, 1, mblk,      ks, lane));
        ldm_x4(al1, a_frag_addr(sb, 1, mblk + 16, ks, lane));
        #pragma unroll
        for (int p = 0; p < 4; ++p) {
            uint4 bh = lds128(wb + p * 512);
            uint4 bl = lds128(wb + 8192 + p * 512);
            // hi * hi
            mma_bf16(acc[0][2 * p],     ah0, bh.x, bh.y);
            mma_bf16(acc[1][2 * p],     ah1, bh.x, bh.y);
            mma_bf16(acc[0][2 * p + 1], ah0, bh.z, bh.w);
            mma_bf16(acc[1][2 * p + 1], ah1, bh.z, bh.w);
            // hi * lo
            mma_bf16(acc[0][2 * p],     ah0, bl.x, bl.y);
            mma_bf16(acc[1][2 * p],     ah1, bl.x, bl.y);
            mma_bf16(acc[0][2 * p + 1], ah0, bl.z, bl.w);
            mma_bf16(acc[1][2 * p + 1], ah1, bl.z, bl.w);
            // lo * hi
            mma_bf16(acc[0][2 * p],     al0, bh.x, bh.y);
            mma_bf16(acc[1][2 * p],     al1, bh.x, bh.y);
            mma_bf16(acc[0][2 * p + 1], al0, bh.z, bh.w);
            mma_bf16(acc[1][2 * p + 1], al1, bh.z, bh.w);
        }
    }

    // ---- epilogue: bias add + capsule interleave (8 data + 8 zero floats) ----
    const float* bias = (const float*)smem;
    const float2 z2 = make_float2(0.f, 0.f);
    #pragma unroll
    for (int nt = 0; nt < 8; ++nt) {
        float2 bc = *(const float2*)(bias + g * 64 + nt * 8 + (lane & 3) * 2);
        const int cap = g * 8 + nt;
        #pragma unroll
        for (int mt = 0; mt < 2; ++mt) {
            #pragma unroll
            for (int hf = 0; hf < 2; ++hf) {
                long row = row0 + mblk + mt * 16 + (lane >> 2) + hf * 8;
                float2 d;
                d.x = acc[mt][nt][hf * 2 + 0] + bc.x;
                d.y = acc[mt][nt][hf * 2 + 1] + bc.y;
                float* pr = out + row * 512 + cap * 16 + (lane & 3) * 2;
                *(float2*)pr = d;
                *(float2*)(pr + 8) = z2;
            }
        }
    }
}

// ---------------------------------------------------------------------------
// Launch
// ---------------------------------------------------------------------------
extern "C" void kernel_launch(void* const* d_in, const int* in_sizes, int n_in,
                              void* d_out, int out_size) {
    const float* xs = (const float*)d_in[0];   // x_scalar [B,256]
    const float* xv = (const float*)d_in[1];   // x_vector [B,128,3]
    const float* Ws = (const float*)d_in[2];   // W_s [256,256]
    const float* bs = (const float*)d_in[3];   // b_s [256]
    float* out = (float*)d_out;

    int Btot = in_sizes[0] / KDIM;

    prep_W_kernel<<<(KDIM * NDIM + 255) / 256, 256>>>(Ws);

    cudaFuncSetAttribute(caps_kernel,
                         cudaFuncAttributeMaxDynamicSharedMemorySize, SMEM_TOTAL);
    caps_kernel<<<GRID_ALL, NTHREADS, SMEM_TOTAL>>>(xs, xv, bs, out, Btot);
}

// round 16
// speedup vs baseline: 1.2324x; 1.0735x over previous
#include <cuda_runtime.h>
#include <cuda_bf16.h>
#include <stdint.h>

// ---------------------------------------------------------------------------
// C[B,256] = x_scalar[B,256] @ W_s[256,256] + b_s
// out = [caps: B x 32 x 16 (cols 0..7 = C slice, 8..15 = 0)] ++ [x_vector copy]
// W_v / b_v dead (e3nn TP output identically zero).
// bf16 hi/lo 3-pass split for fp32-grade accuracy through HMMA.
//
// Role-specialized grid (bid%3==2 -> pure x_vector copy CTA) +
// BARRIER-FREE GEMM mainloop: W fragments pre-packed in per-lane mma layout
// and loaded by each warp via LDG.128 straight from L2 into registers.
// No cp.async, no W smem, no per-kstep __syncthreads -- warps run the whole
// K loop independently, covering each other's latency.
// ---------------------------------------------------------------------------
#define KDIM      256
#define NDIM      256
#define TILE_M    64
#define NTHREADS  256
#define GRID_GEMM 2048
#define GRID_COPY 1024
#define GRID_ALL  (GRID_GEMM + GRID_COPY)

// Dynamic smem layout (65.5 KB/CTA)
#define SM_BIAS   0                       // 1024 B
#define SM_A      1024                    // 2 splits x 32 KB (64 rows x 512 B, swizzled)
#define SMEM_TOTAL (SM_A + 65536)         // 66560 B

// Pre-packed W fragments (B operand of mma.m16n8k16, hi/lo bf16 splits)
// byte offset of a fragment element: ks*8192 + g*2048 + p*512 + lane*16
__device__ __align__(16) unsigned char g_Bhi[131072];
__device__ __align__(16) unsigned char g_Blo[131072];

// ---------------------------------------------------------------------------
// helpers
// ---------------------------------------------------------------------------
__device__ __forceinline__ uint32_t smem_u32(const void* p) {
    uint32_t a;
    asm("{ .reg .u64 t; cvta.to.shared.u64 t, %1; cvt.u32.u64 %0, t; }" : "=r"(a) : "l"(p));
    return a;
}
__device__ __forceinline__ uint32_t pack_bf16x2(float x, float y) {
    __nv_bfloat162 t;
    t.x = __float2bfloat16(x);
    t.y = __float2bfloat16(y);
    return *(uint32_t*)&t;
}
__device__ __forceinline__ void ldm_x4(uint32_t* r, uint32_t addr) {
    asm volatile("ldmatrix.sync.aligned.m8n8.x4.shared.b16 {%0,%1,%2,%3}, [%4];"
                 : "=r"(r[0]), "=r"(r[1]), "=r"(r[2]), "=r"(r[3]) : "r"(addr));
}
__device__ __forceinline__ uint4 ldg128(const void* p) {
    uint4 v;
    asm volatile("ld.global.nc.v4.u32 {%0,%1,%2,%3}, [%4];"
                 : "=r"(v.x), "=r"(v.y), "=r"(v.z), "=r"(v.w) : "l"(p));
    return v;
}
__device__ __forceinline__ void mma_bf16(float* c, const uint32_t* a, uint32_t b0, uint32_t b1) {
    asm volatile("mma.sync.aligned.m16n8k16.row.col.f32.bf16.bf16.f32 "
                 "{%0,%1,%2,%3}, {%4,%5,%6,%7}, {%8,%9}, {%0,%1,%2,%3};"
                 : "+f"(c[0]), "+f"(c[1]), "+f"(c[2]), "+f"(c[3])
                 : "r"(a[0]), "r"(a[1]), "r"(a[2]), "r"(a[3]), "r"(b0), "r"(b1));
}

// A-tile smem address: per split, 512 B rows, 16B-granule XOR swizzle
__device__ __forceinline__ uint32_t a_frag_addr(uint32_t sb, int split, int mrow,
                                                int ks, int lane) {
    int i   = lane & 7;
    int sel = lane >> 3;
    int row = mrow + i + ((sel & 1) << 3);
    int gl  = (ks << 1) + (sel >> 1);
    return sb + SM_A + split * 32768 + row * 512 + ((gl ^ (row & 7)) << 4);
}

// ---------------------------------------------------------------------------
// Prologue: pack W_s (fp32 [K][N]) into bf16 hi/lo B-fragment layout.
// 16B unit index = ((ks*4 + g)*4 + p)*32 + lane
// ---------------------------------------------------------------------------
__global__ void prep_W_kernel(const float* __restrict__ Ws) {
    int idx = blockIdx.x * blockDim.x + threadIdx.x;
    if (idx >= KDIM * NDIM) return;
    int k = idx >> 8;
    int n = idx & 255;
    float w = Ws[idx];
    __nv_bfloat16 hi = __float2bfloat16(w);
    __nv_bfloat16 lo = __float2bfloat16(w - __bfloat162float(hi));

    int ks = k >> 4, kr = k & 15;
    int lane = (n & 7) * 4 + ((kr & 7) >> 1);
    int g = n >> 6;
    int p = (n >> 4) & 3;
    int t = (n >> 3) & 1;
    uint32_t off = (uint32_t)((((ks * 4 + g) * 4 + p) * 32 + lane) * 16
                              + t * 8 + ((kr >> 3) << 2) + ((kr & 1) << 1));
    *(__nv_bfloat16*)(g_Bhi + off) = hi;
    *(__nv_bfloat16*)(g_Blo + off) = lo;
}

// ---------------------------------------------------------------------------
// Main kernel
// ---------------------------------------------------------------------------
__global__ __launch_bounds__(NTHREADS, 2)
void caps_kernel(const float* __restrict__ xs,
                 const float* __restrict__ xv,
                 const float* __restrict__ bs,
                 float* __restrict__ out,
                 int Btot) {
    const int bid = blockIdx.x;
    const int tid = threadIdx.x;

    // ======================= COPY CTA (bid % 3 == 2) =======================
    if ((bid % 3) == 2) {
        const int cid = bid / 3;                    // 0..1023
        const float4* __restrict__ vsrc = (const float4*)xv;
        float4* __restrict__ vdst = (float4*)(out + (long)Btot * 512);
        const long per = (long)Btot * 96 / GRID_COPY;   // 12288 for B=131072
        long base = (long)cid * per + tid;
        const long end = (long)cid * per + per;
        #pragma unroll 4
        for (long i = base; i < end; i += NTHREADS)
            vdst[i] = vsrc[i];
        return;
    }

    // ======================= GEMM CTA ======================================
    extern __shared__ char smem[];
    const uint32_t sb = smem_u32(smem);
    const int wid  = tid >> 5;
    const int lane = tid & 31;
    const int g    = wid & 3;          // N group (64 cols)
    const int mblk = (wid >> 2) * 32;  // M block
    const int gid  = (bid / 3) * 2 + (bid % 3);   // 0..2047 dense GEMM index
    const long row0 = (long)gid * TILE_M;

    // bias -> smem
    ((float*)smem)[tid] = bs[tid];

    // ---- stage A tile: fp32 -> bf16 hi/lo, swizzled smem ----
    #pragma unroll
    for (int j = 0; j < 16; ++j) {
        int idx = tid + j * NTHREADS;          // 0..4095 float4
        int row = idx >> 6;
        int k   = (idx & 63) << 2;
        float4 v = *(const float4*)(xs + (row0 + row) * KDIM + k);
        uint32_t h01 = pack_bf16x2(v.x, v.y);
        uint32_t h23 = pack_bf16x2(v.z, v.w);
        float hx = __bfloat162float(__float2bfloat16(v.x));
        float hy = __bfloat162float(__float2bfloat16(v.y));
        float hz = __bfloat162float(__float2bfloat16(v.z));
        float hw = __bfloat162float(__float2bfloat16(v.w));
        uint32_t l01 = pack_bf16x2(v.x - hx, v.y - hy);
        uint32_t l23 = pack_bf16x2(v.z - hz, v.w - hw);
        int gl = k >> 3;
        uint32_t off = (uint32_t)(row * 512 + ((gl ^ (row & 7)) << 4) + ((k & 7) << 1));
        *(uint2*)(smem + SM_A + off)         = make_uint2(h01, h23);
        *(uint2*)(smem + SM_A + 32768 + off) = make_uint2(l01, l23);
    }

    float acc[2][8][4];
    #pragma unroll
    for (int a = 0; a < 2; ++a)
        #pragma unroll
        for (int b = 0; b < 8; ++b)
            #pragma unroll
            for (int c = 0; c < 4; ++c) acc[a][b][c] = 0.f;

    __syncthreads();          // A tile ready -- the ONLY barrier in the kernel

    // per-warp W fragment base (same data for the 2 warps sharing g; L2 hit)
    const char* __restrict__ wh = (const char*)g_Bhi + g * 2048 + lane * 16;
    const char* __restrict__ wl = (const char*)g_Blo + g * 2048 + lane * 16;

    // ---- barrier-free mainloop: 16 ksteps ----
    #pragma unroll 2
    for (int ks = 0; ks < 16; ++ks) {
        const char* wbh = wh + ks * 8192;
        const char* wbl = wl + ks * 8192;
        // issue all 8 B loads (MLP=8 into L2) and 4 A ldmatrix up front
        uint4 bh0 = ldg128(wbh);
        uint4 bh1 = ldg128(wbh + 512);
        uint4 bh2 = ldg128(wbh + 1024);
        uint4 bh3 = ldg128(wbh + 1536);
        uint4 bl0 = ldg128(wbl);
        uint4 bl1 = ldg128(wbl + 512);
        uint4 bl2 = ldg128(wbl + 1024);
        uint4 bl3 = ldg128(wbl + 1536);
        uint32_t ah0[4], ah1[4], al0[4], al1[4];
        ldm_x4(ah0, a_frag_addr(sb, 0, mblk,      ks, lane));
        ldm_x4(ah1, a_frag_addr(sb, 0, mblk + 16, ks, lane));
        ldm_x4(al0, a_frag_addr(sb, 1, mblk,      ks, lane));
        ldm_x4(al1, a_frag_addr(sb, 1, mblk + 16, ks, lane));

        // p = 0
        mma_bf16(acc[0][0], ah0, bh0.x, bh0.y);
        mma_bf16(acc[1][0], ah1, bh0.x, bh0.y);
        mma_bf16(acc[0][1], ah0, bh0.z, bh0.w);
        mma_bf16(acc[1][1], ah1, bh0.z, bh0.w);
        mma_bf16(acc[0][0], ah0, bl0.x, bl0.y);
        mma_bf16(acc[1][0], ah1, bl0.x, bl0.y);
        mma_bf16(acc[0][1], ah0, bl0.z, bl0.w);
        mma_bf16(acc[1][1], ah1, bl0.z, bl0.w);
        mma_bf16(acc[0][0], al0, bh0.x, bh0.y);
        mma_bf16(acc[1][0], al1, bh0.x, bh0.y);
        mma_bf16(acc[0][1], al0, bh0.z, bh0.w);
        mma_bf16(acc[1][1], al1, bh0.z, bh0.w);
        // p = 1
        mma_bf16(acc[0][2], ah0, bh1.x, bh1.y);
        mma_bf16(acc[1][2], ah1, bh1.x, bh1.y);
        mma_bf16(acc[0][3], ah0, bh1.z, bh1.w);
        mma_bf16(acc[1][3], ah1, bh1.z, bh1.w);
        mma_bf16(acc[0][2], ah0, bl1.x, bl1.y);
        mma_bf16(acc[1][2], ah1, bl1.x, bl1.y);
        mma_bf16(acc[0][3], ah0, bl1.z, bl1.w);
        mma_bf16(acc[1][3], ah1, bl1.z, bl1.w);
        mma_bf16(acc[0][2], al0, bh1.x, bh1.y);
        mma_bf16(acc[1][2], al1, bh1.x, bh1.y);
        mma_bf16(acc[0][3], al0, bh1.z, bh1.w);
        mma_bf16(acc[1][3], al1, bh1.z, bh1.w);
        // p = 2
        mma_bf16(acc[0][4], ah0, bh2.x, bh2.y);
        mma_bf16(acc[1][4], ah1, bh2.x, bh2.y);
        mma_bf16(acc[0][5], ah0, bh2.z, bh2.w);
        mma_bf16(acc[1][5], ah1, bh2.z, bh2.w);
        mma_bf16(acc[0][4], ah0, bl2.x, bl2.y);
        mma_bf16(acc[1][4], ah1, bl2.x, bl2.y);
        mma_bf16(acc[0][5], ah0, bl2.z, bl2.w);
        mma_bf16(acc[1][5], ah1, bl2.z, bl2.w);
        mma_bf16(acc[0][4], al0, bh2.x, bh2.y);
        mma_bf16(acc[1][4], al1, bh2.x, bh2.y);
        mma_bf16(acc[0][5], al0, bh2.z, bh2.w);
        mma_bf16(acc[1][5], al1, bh2.z, bh2.w);
        // p = 3
        mma_bf16(acc[0][6], ah0, bh3.x, bh3.y);
        mma_bf16(acc[1][6], ah1, bh3.x, bh3.y);
        mma_bf16(acc[0][7], ah0, bh3.z, bh3.w);
        mma_bf16(acc[1][7], ah1, bh3.z, bh3.w);
        mma_bf16(acc[0][6], ah0, bl3.x, bl3.y);
        mma_bf16(acc[1][6], ah1, bl3.x, bl3.y);
        mma_bf16(acc[0][7], ah0, bl3.z, bl3.w);
        mma_bf16(acc[1][7], ah1, bl3.z, bl3.w);
        mma_bf16(acc[0][6], al0, bh3.x, bh3.y);
        mma_bf16(acc[1][6], al1, bh3.x, bh3.y);
        mma_bf16(acc[0][7], al0, bh3.z, bh3.w);
        mma_bf16(acc[1][7], al1, bh3.z, bh3.w);
    }

    // ---- epilogue: bias add + capsule interleave (8 data + 8 zero floats) ----
    const float* bias = (const float*)smem;
    const float2 z2 = make_float2(0.f, 0.f);
    #pragma unroll
    for (int nt = 0; nt < 8; ++nt) {
        float2 bc = *(const float2*)(bias + g * 64 + nt * 8 + (lane & 3) * 2);
        const int cap = g * 8 + nt;
        #pragma unroll
        for (int mt = 0; mt < 2; ++mt) {
            #pragma unroll
            for (int hf = 0; hf < 2; ++hf) {
                long row = row0 + mblk + mt * 16 + (lane >> 2) + hf * 8;
                float2 d;
                d.x = acc[mt][nt][hf * 2 + 0] + bc.x;
                d.y = acc[mt][nt][hf * 2 + 1] + bc.y;
                float* pr = out + row * 512 + cap * 16 + (lane & 3) * 2;
                *(float2*)pr = d;
                *(float2*)(pr + 8) = z2;
            }
        }
    }
}

// ---------------------------------------------------------------------------
// Launch
// ---------------------------------------------------------------------------
extern "C" void kernel_launch(void* const* d_in, const int* in_sizes, int n_in,
                              void* d_out, int out_size) {
    const float* xs = (const float*)d_in[0];   // x_scalar [B,256]
    const float* xv = (const float*)d_in[1];   // x_vector [B,128,3]
    const float* Ws = (const float*)d_in[2];   // W_s [256,256]
    const float* bs = (const float*)d_in[3];   // b_s [256]
    float* out = (float*)d_out;

    int Btot = in_sizes[0] / KDIM;

    prep_W_kernel<<<(KDIM * NDIM + 255) / 256, 256>>>(Ws);

    cudaFuncSetAttribute(caps_kernel,
                         cudaFuncAttributeMaxDynamicSharedMemorySize, SMEM_TOTAL);
    caps_kernel<<<GRID_ALL, NTHREADS, SMEM_TOTAL>>>(xs, xv, bs, out, Btot);
}